// round 14
// baseline (speedup 1.0000x reference)
#include <cuda_runtime.h>
#include <cstdint>

#define S_LEN 2048
#define BATCH 32
#define IDIM  256
#define HDIM  512
#define CL    8            // cluster size
#define THREADS_R 512

typedef unsigned long long ull;

// ---------------- PTX helpers ----------------
__device__ __forceinline__ ull pack2(float x, float y) {
    ull r; asm("mov.b64 %0, {%1, %2};" : "=l"(r) : "f"(x), "f"(y)); return r;
}
__device__ __forceinline__ void unpack2(ull v, float &x, float &y) {
    asm("mov.b64 {%0, %1}, %2;" : "=f"(x), "=f"(y) : "l"(v));
}
__device__ __forceinline__ void ffma2(ull &d, ull a, ull b) {
    asm("fma.rn.f32x2 %0, %1, %2, %0;" : "+l"(d) : "l"(a), "l"(b));
}
__device__ __forceinline__ uint32_t smem_u32(const void* p) {
    return (uint32_t)__cvta_generic_to_shared(p);
}
__device__ __forceinline__ uint32_t mapa_addr(uint32_t laddr, uint32_t rank) {
    uint32_t raddr;
    asm("mapa.shared::cluster.u32 %0, %1, %2;" : "=r"(raddr) : "r"(laddr), "r"(rank));
    return raddr;
}
// plain 4B remote smem store (fire-and-forget)
__device__ __forceinline__ void st_cluster_f32(uint32_t raddr, float v) {
    asm volatile("st.shared::cluster.b32 [%0], %1;"
                 :: "r"(raddr), "r"(__float_as_uint(v)) : "memory");
}
__device__ __forceinline__ void mbar_init(uint32_t mbar, uint32_t cnt) {
    asm volatile("mbarrier.init.shared.b64 [%0], %1;" :: "r"(mbar), "r"(cnt) : "memory");
}
__device__ __forceinline__ void mbar_arrive_cluster(uint32_t raddr) {
    asm volatile("mbarrier.arrive.release.cluster.shared::cluster.b64 _, [%0];"
                 :: "r"(raddr) : "memory");
}
__device__ __forceinline__ void mbar_wait_cl(uint32_t mbar, uint32_t parity) {
    uint32_t done;
    asm volatile("{\n\t.reg .pred p;\n\t"
                 "mbarrier.try_wait.parity.acquire.cluster.shared::cta.b64 p, [%1], %2;\n\t"
                 "selp.b32 %0, 1, 0, p;\n\t}"
                 : "=r"(done) : "r"(mbar), "r"(parity) : "memory");
    if (!done) {
        asm volatile("{\n\t.reg .pred P1;\n\t"
                     "WL%=:\n\t"
                     "mbarrier.try_wait.parity.acquire.cluster.shared::cta.b64 P1, [%0], %1, 0x989680;\n\t"
                     "@P1 bra.uni WD%=;\n\t"
                     "bra.uni WL%=;\n\t"
                     "WD%=:\n\t}"
                     :: "r"(mbar), "r"(parity) : "memory");
    }
}
__device__ __forceinline__ void cluster_sync_() {
    asm volatile("barrier.cluster.arrive.aligned;" ::: "memory");
    asm volatile("barrier.cluster.wait.aligned;"   ::: "memory");
}

// =====================================================================
// Phase 1: z = inputs @ Wih^T + (bih + bhh), in-place into d_out.
// (unchanged — f32x2 packed inner product)
// =====================================================================
#define BM 64
#define BN 64
#define BK 32

__global__ __launch_bounds__(256) void zproj_kernel(
    const float* __restrict__ A, const float* __restrict__ W,
    const float* __restrict__ bih, const float* __restrict__ bhh,
    float* __restrict__ C)
{
    __shared__ __align__(16) float As[BK][BM + 8];
    __shared__ __align__(16) float Bs[BK][BN + 8];
    const int tid = threadIdx.x;
    const int m0 = blockIdx.x * BM;
    const int n0 = blockIdx.y * BN;
    const int tx = tid & 15;
    const int ty = tid >> 4;
    ull acc01[4] = {0,0,0,0};
    ull acc23[4] = {0,0,0,0};

    for (int k0 = 0; k0 < IDIM; k0 += BK) {
        #pragma unroll
        for (int i = 0; i < 2; i++) {
            int s  = tid + i * 256;
            int m  = s >> 3;
            int kq = (s & 7) << 2;
            float4 a = *(const float4*)(A + (size_t)(m0 + m) * IDIM + k0 + kq);
            As[kq+0][m] = a.x; As[kq+1][m] = a.y; As[kq+2][m] = a.z; As[kq+3][m] = a.w;
            float4 b = *(const float4*)(W + (size_t)(n0 + m) * IDIM + k0 + kq);
            Bs[kq+0][m] = b.x; Bs[kq+1][m] = b.y; Bs[kq+2][m] = b.z; Bs[kq+3][m] = b.w;
        }
        __syncthreads();
        #pragma unroll
        for (int k = 0; k < BK; k++) {
            float4 a4 = *(const float4*)&As[k][ty * 4];
            const ull* bp = (const ull*)&Bs[k][tx * 4];
            ull b01 = bp[0], b23 = bp[1];
            ull a0 = pack2(a4.x, a4.x);
            ull a1 = pack2(a4.y, a4.y);
            ull a2 = pack2(a4.z, a4.z);
            ull a3 = pack2(a4.w, a4.w);
            ffma2(acc01[0], a0, b01); ffma2(acc23[0], a0, b23);
            ffma2(acc01[1], a1, b01); ffma2(acc23[1], a1, b23);
            ffma2(acc01[2], a2, b01); ffma2(acc23[2], a2, b23);
            ffma2(acc01[3], a3, b01); ffma2(acc23[3], a3, b23);
        }
        __syncthreads();
    }

    float bias[4];
    #pragma unroll
    for (int j = 0; j < 4; j++)
        bias[j] = bih[n0 + tx * 4 + j] + bhh[n0 + tx * 4 + j];

    #pragma unroll
    for (int i = 0; i < 4; i++) {
        float4 o;
        unpack2(acc01[i], o.x, o.y);
        unpack2(acc23[i], o.z, o.w);
        o.x += bias[0]; o.y += bias[1]; o.z += bias[2]; o.w += bias[3];
        *(float4*)(C + (size_t)(m0 + ty * 4 + i) * HDIM + n0 + tx * 4) = o;
    }
}

// =====================================================================
// Phase 2: same exchange as R11 (plain remote scatter + per-source
// count barriers), matvec restructured for latency hiding:
// 512 threads / 16 warps; warp w -> (chunk c = w&7, rowgroup g = w>>3);
// lane l owns row g*32+l of this CTA's 64-row slice, k in [64c,64c+64),
// BOTH batches. W per thread = 32 ull (64 regs) -> ~120 regs total,
// 4 warps/SMSP to hide LDS latency; ptxas has headroom to batch loads.
// =====================================================================
__global__ void __cluster_dims__(CL, 1, 1) __launch_bounds__(THREADS_R, 1)
rnn_scan_kernel(const float* __restrict__ Whh,
                const float* __restrict__ h0,
                float* __restrict__ out)
{
    __shared__ __align__(16) float hbuf[2][2][HDIM];   // [buf][batch][row], full local h
    __shared__ __align__(16) float red[8][132];        // [chunk][batch*64+row] (+pad)
    __shared__ __align__(8)  ull mbarS[2][CL];         // [buf][src], count=1

    const int tid = threadIdx.x;
    const int w   = tid >> 5;
    const int l   = tid & 31;
    const int c   = w & 7;               // k-chunk (and source rank consumed)
    const int g   = w >> 3;              // row-group 0/1
    const int rloc = g * 32 + l;         // row within own 64-row slice
    uint32_t rank; asm("mov.u32 %0, %%cluster_ctarank;" : "=r"(rank));
    const int b0 = (blockIdx.x / CL) * 2;

    const uint32_t mloc = smem_u32(&mbarS[0][0]);
    const uint32_t hloc = smem_u32(&hbuf[0][0][0]);

    // ---- W row slice into regs: row rank*64+rloc, k in [64c, 64c+64) ----
    const ull* wr = (const ull*)(Whh + (size_t)((int)rank * 64 + rloc) * HDIM + c * 64);
    ull wreg[32];
    #pragma unroll
    for (int j = 0; j < 32; j++) wreg[j] = wr[j];

    // ---- init: FULL h0 (both batches) into local buf 0; barriers ----
    for (int gg = tid; gg < HDIM; gg += THREADS_R) {
        hbuf[0][0][gg] = h0[(size_t)b0 * HDIM + gg];
        hbuf[0][1][gg] = h0[(size_t)(b0 + 1) * HDIM + gg];
    }
    if (tid < 2 * CL) mbar_init(mloc + tid * 8u, 1);
    __syncthreads();
    cluster_sync_();   // inits visible cluster-wide before any remote traffic

    // ---- reducer identity (tid < 128): (batch pb, own-slice row rr) ----
    size_t zoff = 0, foff = 0;
    float z_cur = 0.f;
    int pb = 0, rr = 0;
    uint32_t pushoff = 0;
    if (tid < 128) {
        pb = tid >> 6; rr = tid & 63;
        const int grow = (int)rank * 64 + rr;
        zoff = ((size_t)(b0 + pb) * S_LEN) * HDIM + grow;
        foff = (size_t)BATCH * S_LEN * HDIM + (size_t)(b0 + pb) * HDIM + grow;
        z_cur = out[zoff];           // z[t=0] prefetch
        pushoff = (uint32_t)(pb * HDIM + grow) * 4u;   // byte offset within a buffer
    }

    // ---- arrive targets: lane r arrives at rank r's mbar[.][myrank] ----
    uint32_t arrA = 0;
    if (tid < CL) arrA = mapa_addr(mloc, (uint32_t)tid) + rank * 8u;

    uint32_t p0 = 0, p1 = 0;
    for (int t = 0; t < S_LEN; t++) {
        const int cur = t & 1;
        const int nxt = cur ^ 1;
        // prefetch z_{t+1} (last iter reads in-bounds tail region)
        float z_next = z_cur;
        if (tid < 128) z_next = out[zoff + HDIM];

        if (t > 0) {   // warp (g,c) waits only for source CTA c's slice of buf[cur]
            if (cur) { mbar_wait_cl(mloc + (8 + c) * 8u, p1); p1 ^= 1; }
            else     { mbar_wait_cl(mloc + c * 8u,       p0); p0 ^= 1; }
        }

        // ---- matvec partial: row rloc, chunk c, both batches (local LDS) ----
        const ulonglong2* hb0 = (const ulonglong2*)&hbuf[cur][0][c * 64];
        const ulonglong2* hb1 = (const ulonglong2*)&hbuf[cur][1][c * 64];
        ull acc0 = 0, acc1 = 0;
        #pragma unroll
        for (int j2 = 0; j2 < 16; j2++) {
            ulonglong2 u0 = hb0[j2];
            ulonglong2 u1 = hb1[j2];
            ffma2(acc0, wreg[2*j2],   u0.x);
            ffma2(acc1, wreg[2*j2],   u1.x);
            ffma2(acc0, wreg[2*j2+1], u0.y);
            ffma2(acc1, wreg[2*j2+1], u1.y);
        }
        float x, y, s0, s1;
        unpack2(acc0, x, y); s0 = x + y;   // batch0 partial
        unpack2(acc1, x, y); s1 = x + y;   // batch1 partial

        red[c][rloc]      = s0;
        red[c][64 + rloc] = s1;
        __syncthreads();

        if (tid < 128) {
            float s = z_cur;
            #pragma unroll
            for (int q = 0; q < 8; q++) s += red[q][pb * 64 + rr];
            float v = fmaxf(s, 0.f);
            out[zoff] = v;                          // h_t overwrites z_t
            if (t == S_LEN - 1) out[foff] = v;
            if (t < S_LEN - 1) {
                const uint32_t off = (uint32_t)nxt * 4096u + pushoff;
                #pragma unroll
                for (uint32_t r = 0; r < CL; r++)   // scatter to all ranks (incl. self)
                    st_cluster_f32(mapa_addr(hloc + off, r), v);
            }
            z_cur = z_next;
            zoff += HDIM;
        }
        __syncthreads();   // all pushes issued (CTA-cumulative) before release-arrive

        if (tid < CL && t < S_LEN - 1)
            mbar_arrive_cluster(arrA + (uint32_t)nxt * (CL * 8u));
    }
    cluster_sync_();       // keep smem alive until all inbound ops consumed
}

// =====================================================================
extern "C" void kernel_launch(void* const* d_in, const int* in_sizes, int n_in,
                              void* d_out, int out_size) {
    (void)in_sizes; (void)n_in; (void)out_size;
    const float* inputs = (const float*)d_in[0];
    const float* h0     = (const float*)d_in[1];
    const float* Wih    = (const float*)d_in[2];
    const float* Whh    = (const float*)d_in[3];
    const float* bih    = (const float*)d_in[4];
    const float* bhh    = (const float*)d_in[5];
    float* out = (float*)d_out;

    dim3 g1((BATCH * S_LEN) / BM, HDIM / BN);
    zproj_kernel<<<g1, 256>>>(inputs, Wih, bih, bhh, out);
    rnn_scan_kernel<<<(BATCH / 2) * CL, THREADS_R>>>(Whh, h0, out);
}